// round 2
// baseline (speedup 1.0000x reference)
#include <cuda_runtime.h>
#include <math.h>

#define NPTS 65536
#define NN1  16384
#define NN2  8192
#define KNN  16

// Intermediate activations (device globals — no allocation allowed)
__device__ float g_h [NPTS * 32];   // down output
__device__ float g_h1[NN1  * 64];   // conv1 output
__device__ float g_h2[NN2  * 128];  // conv2 output

// ---------------------------------------------------------------------------
// down: h = relu(x @ W_down + b_down)   [65536,64] @ [64,32]
// ---------------------------------------------------------------------------
__global__ void __launch_bounds__(256)
down_kernel(const float* __restrict__ x,
            const float* __restrict__ W,
            const float* __restrict__ b) {
    __shared__ float sW[64 * 32];
    __shared__ float sb[32];
    int tid = threadIdx.x;
    for (int i = tid; i < 64 * 32; i += blockDim.x) sW[i] = W[i];
    if (tid < 32) sb[tid] = b[tid];
    __syncthreads();

    int p = blockIdx.x * blockDim.x + tid;
    if (p >= NPTS) return;

    float xr[64];
    const float4* xp = (const float4*)(x + (size_t)p * 64);
#pragma unroll
    for (int i = 0; i < 16; i++) {
        float4 v = xp[i];
        xr[4*i+0] = v.x; xr[4*i+1] = v.y; xr[4*i+2] = v.z; xr[4*i+3] = v.w;
    }
#pragma unroll
    for (int o = 0; o < 32; o++) {
        float a = sb[o];
#pragma unroll
        for (int i = 0; i < 64; i++) a += xr[i] * sW[i * 32 + o];
        g_h[(size_t)p * 32 + o] = fmaxf(a, 0.f);
    }
}

// ---------------------------------------------------------------------------
// conv1: bipartite RandLA conv, in-feat 32, rij 32, F=64. One target per
// block-iteration; persistent blocks, weights staged in static shared (~44KB).
// threads = 128
// ---------------------------------------------------------------------------
__global__ void __launch_bounds__(128)
conv1_kernel(const float* __restrict__ pos,
             const int*   __restrict__ idx1,
             const int*   __restrict__ src1,
             const float* __restrict__ Wpp, const float* __restrict__ bpp,
             const float* __restrict__ Watt, const float* __restrict__ batt,
             const float* __restrict__ Wg,  const float* __restrict__ bg) {
    __shared__ float sWpp[10 * 32];
    __shared__ float sWatt[64 * 64];
    __shared__ float sWg[64 * 64];
    __shared__ float sbpp[32], sbatt[64], sbg[64];
    __shared__ float fij[KNN][64];
    __shared__ float att[KNN][64];
    __shared__ float rel[KNN][10];
    __shared__ float smax[KNN], sinv[KNN];
    __shared__ float agg[64];
    __shared__ int   ssrc[KNN];

    int tid = threadIdx.x;  // 128
    for (int i = tid; i < 10 * 32; i += 128) sWpp[i] = Wpp[i];
    for (int i = tid; i < 64 * 64; i += 128) { sWatt[i] = Watt[i]; sWg[i] = Wg[i]; }
    if (tid < 32) sbpp[tid] = bpp[tid];
    if (tid < 64) { sbatt[tid] = batt[tid]; sbg[tid] = bg[tid]; }
    __syncthreads();

    for (int t = blockIdx.x; t < NN1; t += gridDim.x) {
        int pi = idx1[t];
        float pix = pos[pi*3+0], piy = pos[pi*3+1], piz = pos[pi*3+2];
        if (tid < KNN) {
            int s = src1[t * KNN + tid];
            ssrc[tid] = s;
            float pjx = pos[s*3+0], pjy = pos[s*3+1], pjz = pos[s*3+2];
            float vx = pix - pjx, vy = piy - pjy, vz = piz - pjz;
            rel[tid][0] = pix; rel[tid][1] = piy; rel[tid][2] = piz;
            rel[tid][3] = pjx; rel[tid][4] = pjy; rel[tid][5] = pjz;
            rel[tid][6] = vx;  rel[tid][7] = vy;  rel[tid][8] = vz;
            rel[tid][9] = sqrtf(vx*vx + vy*vy + vz*vz);
        }
        __syncthreads();

        // fij = [h[src] (32), relu(rel @ Wpp + bpp) (32)]
        for (int it = tid; it < KNN * 32; it += 128) {
            int e = it >> 5, o = it & 31;
            fij[e][o] = g_h[(size_t)ssrc[e] * 32 + o];
            float a = sbpp[o];
#pragma unroll
            for (int i = 0; i < 10; i++) a += rel[e][i] * sWpp[i * 32 + o];
            fij[e][32 + o] = fmaxf(a, 0.f);
        }
        __syncthreads();

        // att = relu(fij @ Watt + batt): each thread: fixed o, 8 edges blocked
        {
            int o  = tid & 63;
            int e0 = (tid >> 6) * 8;   // 0 or 8
            float acc[8];
#pragma unroll
            for (int j = 0; j < 8; j++) acc[j] = sbatt[o];
#pragma unroll
            for (int i = 0; i < 64; i++) {
                float w = sWatt[i * 64 + o];
#pragma unroll
                for (int j = 0; j < 8; j++) acc[j] += fij[e0 + j][i] * w;
            }
#pragma unroll
            for (int j = 0; j < 8; j++) att[e0 + j][o] = fmaxf(acc[j], 0.f);
        }
        __syncthreads();

        // per-edge softmax stats over feature dim
        if (tid < KNN) {
            float m = -1e30f;
#pragma unroll
            for (int i = 0; i < 64; i++) m = fmaxf(m, att[tid][i]);
            float s = 0.f;
#pragma unroll
            for (int i = 0; i < 64; i++) s += __expf(att[tid][i] - m);
            smax[tid] = m; sinv[tid] = 1.f / s;
        }
        __syncthreads();

        // agg[o] = sum_e softmax(att)[e][o] * fij[e][o]
        if (tid < 64) {
            float a = 0.f;
#pragma unroll
            for (int e = 0; e < KNN; e++)
                a += __expf(att[e][tid] - smax[e]) * sinv[e] * fij[e][tid];
            agg[tid] = a;
        }
        __syncthreads();

        // h1 = relu(agg @ Wg + bg)
        if (tid < 64) {
            float a = sbg[tid];
#pragma unroll
            for (int i = 0; i < 64; i++) a += agg[i] * sWg[i * 64 + tid];
            g_h1[(size_t)t * 64 + tid] = fmaxf(a, 0.f);
        }
        __syncthreads();
    }
}

// ---------------------------------------------------------------------------
// conv2: in-feat 64, rij 64, F=128. Dynamic shared for the 3 big W tensors.
// threads = 512, persistent (1 block/SM due to ~149KB shared).
// ---------------------------------------------------------------------------
#define C2_DYN_FLOATS (10*64 + 128*128 + 128*128)   // 33408

__global__ void __launch_bounds__(512, 1)
conv2_kernel(const float* __restrict__ pos,
             const int*   __restrict__ idx1,
             const int*   __restrict__ idx2,
             const int*   __restrict__ src2,
             const float* __restrict__ Wpp, const float* __restrict__ bpp,
             const float* __restrict__ Watt, const float* __restrict__ batt,
             const float* __restrict__ Wg,  const float* __restrict__ bg) {
    extern __shared__ float dynsmem[];
    float* sWpp  = dynsmem;                 // 640
    float* sWatt = dynsmem + 640;           // 16384
    float* sWg   = sWatt + 128 * 128;       // 16384

    __shared__ float sbpp[64], sbatt[128], sbg[128];
    __shared__ float fij[KNN][128];
    __shared__ float att[KNN][128];
    __shared__ float rel[KNN][10];
    __shared__ float smax[KNN], sinv[KNN];
    __shared__ float agg[128];
    __shared__ int   ssrc[KNN];

    int tid = threadIdx.x;  // 512
    for (int i = tid; i < 10 * 64; i += 512) sWpp[i] = Wpp[i];
    for (int i = tid; i < 128 * 128; i += 512) { sWatt[i] = Watt[i]; sWg[i] = Wg[i]; }
    if (tid < 64)  sbpp[tid] = bpp[tid];
    if (tid < 128) { sbatt[tid] = batt[tid]; sbg[tid] = bg[tid]; }
    __syncthreads();

    for (int t = blockIdx.x; t < NN2; t += gridDim.x) {
        int pidx = idx1[idx2[t]];
        float pix = pos[pidx*3+0], piy = pos[pidx*3+1], piz = pos[pidx*3+2];
        if (tid < KNN) {
            int s = src2[t * KNN + tid];
            ssrc[tid] = s;
            int pj = idx1[s];
            float pjx = pos[pj*3+0], pjy = pos[pj*3+1], pjz = pos[pj*3+2];
            float vx = pix - pjx, vy = piy - pjy, vz = piz - pjz;
            rel[tid][0] = pix; rel[tid][1] = piy; rel[tid][2] = piz;
            rel[tid][3] = pjx; rel[tid][4] = pjy; rel[tid][5] = pjz;
            rel[tid][6] = vx;  rel[tid][7] = vy;  rel[tid][8] = vz;
            rel[tid][9] = sqrtf(vx*vx + vy*vy + vz*vz);
        }
        __syncthreads();

        // fij = [h1[src] (64), relu(rel @ Wpp + bpp) (64)]
        for (int it = tid; it < KNN * 64; it += 512) {
            int e = it >> 6, o = it & 63;
            fij[e][o] = g_h1[(size_t)ssrc[e] * 64 + o];
            float a = sbpp[o];
#pragma unroll
            for (int i = 0; i < 10; i++) a += rel[e][i] * sWpp[i * 64 + o];
            fij[e][64 + o] = fmaxf(a, 0.f);
        }
        __syncthreads();

        // att: fixed o per thread, 4 edges blocked (512 threads = 128 o × 4 groups)
        {
            int o  = tid & 127;
            int e0 = (tid >> 7) * 4;   // 0,4,8,12
            float acc[4];
#pragma unroll
            for (int j = 0; j < 4; j++) acc[j] = sbatt[o];
#pragma unroll
            for (int i = 0; i < 128; i++) {
                float w = sWatt[i * 128 + o];
#pragma unroll
                for (int j = 0; j < 4; j++) acc[j] += fij[e0 + j][i] * w;
            }
#pragma unroll
            for (int j = 0; j < 4; j++) att[e0 + j][o] = fmaxf(acc[j], 0.f);
        }
        __syncthreads();

        if (tid < KNN) {
            float m = -1e30f;
#pragma unroll
            for (int i = 0; i < 128; i++) m = fmaxf(m, att[tid][i]);
            float s = 0.f;
#pragma unroll
            for (int i = 0; i < 128; i++) s += __expf(att[tid][i] - m);
            smax[tid] = m; sinv[tid] = 1.f / s;
        }
        __syncthreads();

        if (tid < 128) {
            float a = 0.f;
#pragma unroll
            for (int e = 0; e < KNN; e++)
                a += __expf(att[e][tid] - smax[e]) * sinv[e] * fij[e][tid];
            agg[tid] = a;
        }
        __syncthreads();

        if (tid < 128) {
            float a = sbg[tid];
#pragma unroll
            for (int i = 0; i < 128; i++) a += agg[i] * sWg[i * 128 + tid];
            g_h2[(size_t)t * 128 + tid] = fmaxf(a, 0.f);
        }
        __syncthreads();
    }
}

// ---------------------------------------------------------------------------
// tail: out = relu(relu(h2@W_up+b_up) + relu(x[idx1[idx2]]@W_sc+b_sc))
// threads = 128, dynamic shared for W_up (64KB) + W_sc (32KB)
// ---------------------------------------------------------------------------
#define TAIL_DYN_FLOATS (128*128 + 64*128)   // 24576

__global__ void __launch_bounds__(128)
tail_kernel(const float* __restrict__ x,
            const int*   __restrict__ idx1,
            const int*   __restrict__ idx2,
            const float* __restrict__ Wup, const float* __restrict__ bup,
            const float* __restrict__ Wsc, const float* __restrict__ bsc,
            float* __restrict__ out) {
    extern __shared__ float dynsmem[];
    float* sWup = dynsmem;               // 16384
    float* sWsc = dynsmem + 128 * 128;   // 8192

    __shared__ float sbup[128], sbsc[128];
    __shared__ float sh2[128], sx[64];

    int tid = threadIdx.x;  // 128
    for (int i = tid; i < 128 * 128; i += 128) sWup[i] = Wup[i];
    for (int i = tid; i < 64 * 128;  i += 128) sWsc[i] = Wsc[i];
    sbup[tid] = bup[tid]; sbsc[tid] = bsc[tid];
    __syncthreads();

    for (int t = blockIdx.x; t < NN2; t += gridDim.x) {
        sh2[tid] = g_h2[(size_t)t * 128 + tid];
        int xr = idx1[idx2[t]];
        if (tid < 64) sx[tid] = x[(size_t)xr * 64 + tid];
        __syncthreads();

        float a = sbup[tid];
#pragma unroll
        for (int i = 0; i < 128; i++) a += sh2[i] * sWup[i * 128 + tid];
        float c = sbsc[tid];
#pragma unroll
        for (int i = 0; i < 64; i++) c += sx[i] * sWsc[i * 128 + tid];
        out[(size_t)t * 128 + tid] = fmaxf(fmaxf(a, 0.f) + fmaxf(c, 0.f), 0.f);
        __syncthreads();
    }
}

// ---------------------------------------------------------------------------
extern "C" void kernel_launch(void* const* d_in, const int* in_sizes, int n_in,
                              void* d_out, int out_size) {
    const float* x      = (const float*)d_in[0];
    const float* pos    = (const float*)d_in[1];
    const float* W_down = (const float*)d_in[2];
    const float* b_down = (const float*)d_in[3];
    const float* W_pp1  = (const float*)d_in[4];
    const float* b_pp1  = (const float*)d_in[5];
    const float* W_att1 = (const float*)d_in[6];
    const float* b_att1 = (const float*)d_in[7];
    const float* W_g1   = (const float*)d_in[8];
    const float* b_g1   = (const float*)d_in[9];
    const float* W_pp2  = (const float*)d_in[10];
    const float* b_pp2  = (const float*)d_in[11];
    const float* W_att2 = (const float*)d_in[12];
    const float* b_att2 = (const float*)d_in[13];
    const float* W_g2   = (const float*)d_in[14];
    const float* b_g2   = (const float*)d_in[15];
    const float* W_up   = (const float*)d_in[16];
    const float* b_up   = (const float*)d_in[17];
    const float* W_sc   = (const float*)d_in[18];
    const float* b_sc   = (const float*)d_in[19];
    const int*   idx1   = (const int*)d_in[20];
    const int*   idx2   = (const int*)d_in[21];
    const int*   src1   = (const int*)d_in[22];
    // d_in[23] = dst1 (implied by contiguity), d_in[25] = dst2: unused
    const int*   src2   = (const int*)d_in[24];
    float* out = (float*)d_out;

    cudaFuncSetAttribute(conv2_kernel, cudaFuncAttributeMaxDynamicSharedMemorySize,
                         C2_DYN_FLOATS * (int)sizeof(float));
    cudaFuncSetAttribute(tail_kernel, cudaFuncAttributeMaxDynamicSharedMemorySize,
                         TAIL_DYN_FLOATS * (int)sizeof(float));

    down_kernel<<<NPTS / 256, 256>>>(x, W_down, b_down);
    conv1_kernel<<<740, 128>>>(pos, idx1, src1,
                               W_pp1, b_pp1, W_att1, b_att1, W_g1, b_g1);
    conv2_kernel<<<148, 512, C2_DYN_FLOATS * sizeof(float)>>>(pos, idx1, idx2, src2,
                               W_pp2, b_pp2, W_att2, b_att2, W_g2, b_g2);
    tail_kernel<<<296, 128, TAIL_DYN_FLOATS * sizeof(float)>>>(x, idx1, idx2,
                               W_up, b_up, W_sc, b_sc, out);
}

// round 3
// speedup vs baseline: 1.3762x; 1.3762x over previous
#include <cuda_runtime.h>
#include <math.h>

#define NPTS 65536
#define NN1  16384
#define NN2  8192
#define KNN  16

typedef unsigned long long u64;

__device__ __forceinline__ u64 pk2(float lo, float hi) {
    u64 r; asm("mov.b64 %0,{%1,%2};" : "=l"(r) : "f"(lo), "f"(hi)); return r;
}
__device__ __forceinline__ u64 pk1(float v) { return pk2(v, v); }
__device__ __forceinline__ float2 upk(u64 v) {
    float2 f; asm("mov.b64 {%0,%1},%2;" : "=f"(f.x), "=f"(f.y) : "l"(v)); return f;
}
__device__ __forceinline__ u64 ff2(u64 a, u64 b, u64 c) {
    u64 d; asm("fma.rn.f32x2 %0,%1,%2,%3;" : "=l"(d) : "l"(a), "l"(b), "l"(c)); return d;
}
__device__ __forceinline__ u64 add2(u64 a, u64 b) {
    u64 d; asm("add.rn.f32x2 %0,%1,%2;" : "=l"(d) : "l"(a), "l"(b)); return d;
}

// Intermediate activations
__device__ float g_h [NPTS * 32];
__device__ float g_h1[(size_t)NN1 * 64];
__device__ float g_h2[(size_t)NN2 * 128];

// ---------------------------------------------------------------------------
// down: h = relu(x @ W_down + b_down)   [65536,64]@[64,32], f32x2 output pairs
// ---------------------------------------------------------------------------
__global__ void __launch_bounds__(256)
down_kernel(const float* __restrict__ x,
            const float* __restrict__ W,
            const float* __restrict__ b) {
    __shared__ float sW[64 * 32];
    __shared__ float sb[32];
    int tid = threadIdx.x;
    for (int i = tid; i < 64 * 32; i += 256) sW[i] = W[i];
    if (tid < 32) sb[tid] = b[tid];
    __syncthreads();

    int p = blockIdx.x * 256 + tid;

    float xr[64];
    const float4* xp = (const float4*)(x + (size_t)p * 64);
#pragma unroll
    for (int i = 0; i < 16; i++) {
        float4 v = xp[i];
        xr[4*i+0] = v.x; xr[4*i+1] = v.y; xr[4*i+2] = v.z; xr[4*i+3] = v.w;
    }
    u64 acc[16];
#pragma unroll
    for (int j = 0; j < 16; j++) acc[j] = pk2(sb[2*j], sb[2*j+1]);
#pragma unroll 4
    for (int i = 0; i < 64; i++) {
        u64 xi = pk1(xr[i]);
        const u64* wr = (const u64*)&sW[i * 32];
#pragma unroll
        for (int j = 0; j < 16; j++) acc[j] = ff2(xi, wr[j], acc[j]);
    }
    float* op = &g_h[(size_t)p * 32];
#pragma unroll
    for (int j = 0; j < 16; j++) {
        float2 v = upk(acc[j]);
        op[2*j]   = fmaxf(v.x, 0.f);
        op[2*j+1] = fmaxf(v.y, 0.f);
    }
}

// ---------------------------------------------------------------------------
// conv1: T=8 targets/iter, 512 threads, persistent grid=148
// dims: in-feat 32, rij 32, F=64; 16 edges/target
// ---------------------------------------------------------------------------
#define FT1 18
#define C1_DYN_FLOATS (320 + 4096 + 4096 + 8*64*FT1 + 8*64*FT1)

__global__ void __launch_bounds__(512, 1)
conv1_kernel(const float* __restrict__ pos,
             const int*   __restrict__ idx1,
             const int*   __restrict__ src1,
             const float* __restrict__ Wpp, const float* __restrict__ bpp,
             const float* __restrict__ Watt, const float* __restrict__ batt,
             const float* __restrict__ Wg,  const float* __restrict__ bg) {
    extern __shared__ float smem[];
    float* sWpp  = smem;                    // 320
    float* sWatt = smem + 320;              // 4096
    float* sWg   = smem + 4416;             // 4096
    float* fijT  = smem + 8512;             // 8*64*18 = 9216  [t][feat][edge]
    float* attT  = smem + 17728;            // 9216            [t][o][edge]

    __shared__ float rel[128][10];
    __shared__ int   ssrc[128];
    __shared__ float sbpp[32], sbatt[64], sbg[64];
    __shared__ float sm[128], sv[128], sP[128][4];
    __shared__ float aggS[8][64];

    int tid = threadIdx.x;
    for (int i = tid; i < 320; i += 512) sWpp[i] = Wpp[i];
    for (int i = tid; i < 4096; i += 512) { sWatt[i] = Watt[i]; sWg[i] = Wg[i]; }
    if (tid < 32) sbpp[tid] = bpp[tid];
    if (tid < 64) { sbatt[tid] = batt[tid]; sbg[tid] = bg[tid]; }
    __syncthreads();

    for (int t0 = blockIdx.x * 8; t0 < NN1; t0 += gridDim.x * 8) {
        // ---- rel + src ----
        if (tid < 128) {
            int t = tid >> 4, e = tid & 15;
            int tgt = t0 + t;
            int pi = idx1[tgt];
            float pix = pos[pi*3+0], piy = pos[pi*3+1], piz = pos[pi*3+2];
            int s = src1[tgt * KNN + e];
            ssrc[tid] = s;
            float pjx = pos[s*3+0], pjy = pos[s*3+1], pjz = pos[s*3+2];
            float vx = pix - pjx, vy = piy - pjy, vz = piz - pjz;
            rel[tid][0] = pix; rel[tid][1] = piy; rel[tid][2] = piz;
            rel[tid][3] = pjx; rel[tid][4] = pjy; rel[tid][5] = pjz;
            rel[tid][6] = vx;  rel[tid][7] = vy;  rel[tid][8] = vz;
            rel[tid][9] = sqrtf(vx*vx + vy*vy + vz*vz);
        }
        __syncthreads();

        // ---- gather h[src] (feats 0..31) + point_pos_nn (feats 32..63), transposed ----
        {
            int et = tid >> 2, sub = tid & 3;
            int t = et >> 4, e = et & 15;
            const float4* hp = (const float4*)&g_h[(size_t)ssrc[et] * 32 + sub * 8];
            float4 v0 = hp[0], v1 = hp[1];
            float* dst = &fijT[(t * 64 + sub * 8) * FT1 + e];
            dst[0*FT1] = v0.x; dst[1*FT1] = v0.y; dst[2*FT1] = v0.z; dst[3*FT1] = v0.w;
            dst[4*FT1] = v1.x; dst[5*FT1] = v1.y; dst[6*FT1] = v1.z; dst[7*FT1] = v1.w;
#pragma unroll
            for (int k = 0; k < 8; k++) {
                int o = sub * 8 + k;
                float a = sbpp[o];
#pragma unroll
                for (int i = 0; i < 10; i++) a += rel[et][i] * sWpp[i * 32 + o];
                fijT[(t * 64 + 32 + o) * FT1 + e] = fmaxf(a, 0.f);
            }
        }
        __syncthreads();

        // ---- att = relu(fij @ Watt + batt), edge-packed f32x2, i-split c=2 ----
        {
            int q  = tid & 15;            // output quad (64/4)
            int eo = (tid >> 4) & 1;      // edge oct (16/8)
            int t  = (tid >> 5) & 7;      // target
            int c  = tid >> 8;            // i-half
            const float4* W4 = (const float4*)sWatt;
            const float* fb = &fijT[(t * 64) * FT1 + 8 * eo];
            u64 acc[16];
#pragma unroll
            for (int j = 0; j < 16; j++) acc[j] = 0ull;
#pragma unroll 4
            for (int ii = 0; ii < 32; ii++) {
                int i = c * 32 + ii;
                float4 w = W4[i * 16 + q];
                u64 w0 = pk1(w.x), w1 = pk1(w.y), w2 = pk1(w.z), w3 = pk1(w.w);
                const float* fr = fb + i * FT1;
                u64 a0 = *(const u64*)&fr[0], a1 = *(const u64*)&fr[2];
                u64 a2 = *(const u64*)&fr[4], a3 = *(const u64*)&fr[6];
                acc[0]  = ff2(a0, w0, acc[0]);  acc[1]  = ff2(a1, w0, acc[1]);
                acc[2]  = ff2(a2, w0, acc[2]);  acc[3]  = ff2(a3, w0, acc[3]);
                acc[4]  = ff2(a0, w1, acc[4]);  acc[5]  = ff2(a1, w1, acc[5]);
                acc[6]  = ff2(a2, w1, acc[6]);  acc[7]  = ff2(a3, w1, acc[7]);
                acc[8]  = ff2(a0, w2, acc[8]);  acc[9]  = ff2(a1, w2, acc[9]);
                acc[10] = ff2(a2, w2, acc[10]); acc[11] = ff2(a3, w2, acc[11]);
                acc[12] = ff2(a0, w3, acc[12]); acc[13] = ff2(a1, w3, acc[13]);
                acc[14] = ff2(a2, w3, acc[14]); acc[15] = ff2(a3, w3, acc[15]);
            }
            float* ab = &attT[(t * 64 + 4 * q) * FT1 + 8 * eo];
            if (c == 1) {
#pragma unroll
                for (int j = 0; j < 4; j++)
#pragma unroll
                    for (int p = 0; p < 4; p++) {
                        float2 v = upk(acc[j*4+p]);
                        ab[j*FT1 + 2*p]   = v.x;
                        ab[j*FT1 + 2*p+1] = v.y;
                    }
            }
            __syncthreads();
            if (c == 0) {
#pragma unroll
                for (int j = 0; j < 4; j++) {
                    float bb = sbatt[4*q+j];
#pragma unroll
                    for (int p = 0; p < 4; p++) {
                        float2 v = upk(acc[j*4+p]);
                        int ix = j*FT1 + 2*p;
                        ab[ix]   = fmaxf(ab[ix]   + v.x + bb, 0.f);
                        ab[ix+1] = fmaxf(ab[ix+1] + v.y + bb, 0.f);
                    }
                }
            }
            __syncthreads();
        }

        // ---- softmax stats per edge over 64 features ----
        {
            int et = tid >> 2, c = tid & 3;
            int t = et >> 4, e = et & 15;
            const float* ac = &attT[(t * 64) * FT1 + e];
            float m = -1e30f;
#pragma unroll 4
            for (int o = c*16; o < c*16+16; o++) m = fmaxf(m, ac[o*FT1]);
            sP[et][c] = m;
            __syncthreads();
            if (tid < 128)
                sm[tid] = fmaxf(fmaxf(sP[tid][0], sP[tid][1]), fmaxf(sP[tid][2], sP[tid][3]));
            __syncthreads();
            float mm = sm[et];
            float s = 0.f;
#pragma unroll 4
            for (int o = c*16; o < c*16+16; o++) s += __expf(ac[o*FT1] - mm);
            sP[et][c] = s;
            __syncthreads();
            if (tid < 128)
                sv[tid] = 1.f / (sP[tid][0] + sP[tid][1] + sP[tid][2] + sP[tid][3]);
            __syncthreads();
        }

        // ---- agg[o] = sum_e softmax * fij ----
        {
            int t = tid >> 6, o = tid & 63;
            const float* ar = &attT[(t * 64 + o) * FT1];
            const float* fr = &fijT[(t * 64 + o) * FT1];
            float a = 0.f;
#pragma unroll
            for (int e = 0; e < 16; e++) {
                int et = t * 16 + e;
                a += __expf(ar[e] - sm[et]) * sv[et] * fr[e];
            }
            aggS[t][o] = a;
        }
        __syncthreads();

        // ---- global: h1 = relu(agg @ Wg + bg), c-split=4 ----
        {
            int t = tid >> 6, q = (tid >> 2) & 15, c = tid & 3;
            u64 s0 = 0ull, s1 = 0ull;
#pragma unroll 4
            for (int ii = 0; ii < 16; ii++) {
                int i = c * 16 + ii;
                u64 xi = pk1(aggS[t][i]);
                s0 = ff2(xi, *(const u64*)&sWg[i*64 + 4*q],     s0);
                s1 = ff2(xi, *(const u64*)&sWg[i*64 + 4*q + 2], s1);
            }
            u64* scr = (u64*)attT;
            if (c) { scr[tid*2] = s0; scr[tid*2+1] = s1; }
            __syncthreads();
            if (c == 0) {
#pragma unroll
                for (int cc = 1; cc < 4; cc++) {
                    s0 = add2(s0, scr[(tid+cc)*2]);
                    s1 = add2(s1, scr[(tid+cc)*2+1]);
                }
                float2 v0 = upk(s0), v1 = upk(s1);
                int o = 4 * q;
                float* op = &g_h1[(size_t)(t0 + t) * 64 + o];
                op[0] = fmaxf(v0.x + sbg[o],   0.f);
                op[1] = fmaxf(v0.y + sbg[o+1], 0.f);
                op[2] = fmaxf(v1.x + sbg[o+2], 0.f);
                op[3] = fmaxf(v1.y + sbg[o+3], 0.f);
            }
            __syncthreads();
        }
    }
}

// ---------------------------------------------------------------------------
// conv2: T=4 targets/iter, 512 threads, grid=148
// dims: in-feat 64, rij 64, F=128; 16 edges/target
// ---------------------------------------------------------------------------
#define FT2 18
#define C2_DYN_FLOATS (640 + 16384 + 16384 + 4*128*FT2 + 4*128*FT2)

__global__ void __launch_bounds__(512, 1)
conv2_kernel(const float* __restrict__ pos,
             const int*   __restrict__ idx1,
             const int*   __restrict__ idx2,
             const int*   __restrict__ src2,
             const float* __restrict__ Wpp, const float* __restrict__ bpp,
             const float* __restrict__ Watt, const float* __restrict__ batt,
             const float* __restrict__ Wg,  const float* __restrict__ bg) {
    extern __shared__ float smem[];
    float* sWpp  = smem;                    // 640
    float* sWatt = smem + 640;              // 16384
    float* sWg   = smem + 17024;            // 16384
    float* fijT  = smem + 33408;            // 4*128*18 = 9216
    float* attT  = smem + 42624;            // 9216

    __shared__ float rel[64][10];
    __shared__ int   ssrc[64];
    __shared__ float sbpp[64], sbatt[128], sbg[128];
    __shared__ float sm[64], sv[64], sP[64][8];
    __shared__ float aggS[4][128];

    int tid = threadIdx.x;
    for (int i = tid; i < 640; i += 512) sWpp[i] = Wpp[i];
    for (int i = tid; i < 16384; i += 512) { sWatt[i] = Watt[i]; sWg[i] = Wg[i]; }
    if (tid < 64)  sbpp[tid] = bpp[tid];
    if (tid < 128) { sbatt[tid] = batt[tid]; sbg[tid] = bg[tid]; }
    __syncthreads();

    for (int t0 = blockIdx.x * 4; t0 < NN2; t0 += gridDim.x * 4) {
        // ---- rel + src ----
        if (tid < 64) {
            int t = tid >> 4, e = tid & 15;
            int tgt = t0 + t;
            int pidx = idx1[idx2[tgt]];
            float pix = pos[pidx*3+0], piy = pos[pidx*3+1], piz = pos[pidx*3+2];
            int s = src2[tgt * KNN + e];
            ssrc[tid] = s;
            int pj = idx1[s];
            float pjx = pos[pj*3+0], pjy = pos[pj*3+1], pjz = pos[pj*3+2];
            float vx = pix - pjx, vy = piy - pjy, vz = piz - pjz;
            rel[tid][0] = pix; rel[tid][1] = piy; rel[tid][2] = piz;
            rel[tid][3] = pjx; rel[tid][4] = pjy; rel[tid][5] = pjz;
            rel[tid][6] = vx;  rel[tid][7] = vy;  rel[tid][8] = vz;
            rel[tid][9] = sqrtf(vx*vx + vy*vy + vz*vz);
        }
        __syncthreads();

        // ---- gather h1[src] (0..63) + pp (64..127), transposed ----
        {
            int et = tid >> 3, sub = tid & 7;
            int t = et >> 4, e = et & 15;
            const float4* hp = (const float4*)&g_h1[(size_t)ssrc[et] * 64 + sub * 8];
            float4 v0 = hp[0], v1 = hp[1];
            float* dst = &fijT[(t * 128 + sub * 8) * FT2 + e];
            dst[0*FT2] = v0.x; dst[1*FT2] = v0.y; dst[2*FT2] = v0.z; dst[3*FT2] = v0.w;
            dst[4*FT2] = v1.x; dst[5*FT2] = v1.y; dst[6*FT2] = v1.z; dst[7*FT2] = v1.w;
#pragma unroll
            for (int k = 0; k < 8; k++) {
                int o = sub * 8 + k;
                float a = sbpp[o];
#pragma unroll
                for (int i = 0; i < 10; i++) a += rel[et][i] * sWpp[i * 64 + o];
                fijT[(t * 128 + 64 + o) * FT2 + e] = fmaxf(a, 0.f);
            }
        }
        __syncthreads();

        // ---- att: [16e x 128o x 128i] per target, i-split c=2 ----
        {
            int q  = (tid & 7) | (((tid >> 5) & 3) << 3);   // 32 output quads
            int eo = (tid >> 3) & 1;                         // edge oct
            int t  = ((tid >> 4) & 1) | (((tid >> 7) & 1) << 1); // 4 targets
            int c  = tid >> 8;                               // i-half
            const float4* W4 = (const float4*)sWatt;
            const float* fb = &fijT[(t * 128) * FT2 + 8 * eo];
            u64 acc[16];
#pragma unroll
            for (int j = 0; j < 16; j++) acc[j] = 0ull;
#pragma unroll 4
            for (int ii = 0; ii < 64; ii++) {
                int i = c * 64 + ii;
                float4 w = W4[i * 32 + q];
                u64 w0 = pk1(w.x), w1 = pk1(w.y), w2 = pk1(w.z), w3 = pk1(w.w);
                const float* fr = fb + i * FT2;
                u64 a0 = *(const u64*)&fr[0], a1 = *(const u64*)&fr[2];
                u64 a2 = *(const u64*)&fr[4], a3 = *(const u64*)&fr[6];
                acc[0]  = ff2(a0, w0, acc[0]);  acc[1]  = ff2(a1, w0, acc[1]);
                acc[2]  = ff2(a2, w0, acc[2]);  acc[3]  = ff2(a3, w0, acc[3]);
                acc[4]  = ff2(a0, w1, acc[4]);  acc[5]  = ff2(a1, w1, acc[5]);
                acc[6]  = ff2(a2, w1, acc[6]);  acc[7]  = ff2(a3, w1, acc[7]);
                acc[8]  = ff2(a0, w2, acc[8]);  acc[9]  = ff2(a1, w2, acc[9]);
                acc[10] = ff2(a2, w2, acc[10]); acc[11] = ff2(a3, w2, acc[11]);
                acc[12] = ff2(a0, w3, acc[12]); acc[13] = ff2(a1, w3, acc[13]);
                acc[14] = ff2(a2, w3, acc[14]); acc[15] = ff2(a3, w3, acc[15]);
            }
            float* ab = &attT[(t * 128 + 4 * q) * FT2 + 8 * eo];
            if (c == 1) {
#pragma unroll
                for (int j = 0; j < 4; j++)
#pragma unroll
                    for (int p = 0; p < 4; p++) {
                        float2 v = upk(acc[j*4+p]);
                        ab[j*FT2 + 2*p]   = v.x;
                        ab[j*FT2 + 2*p+1] = v.y;
                    }
            }
            __syncthreads();
            if (c == 0) {
#pragma unroll
                for (int j = 0; j < 4; j++) {
                    float bb = sbatt[4*q+j];
#pragma unroll
                    for (int p = 0; p < 4; p++) {
                        float2 v = upk(acc[j*4+p]);
                        int ix = j*FT2 + 2*p;
                        ab[ix]   = fmaxf(ab[ix]   + v.x + bb, 0.f);
                        ab[ix+1] = fmaxf(ab[ix+1] + v.y + bb, 0.f);
                    }
                }
            }
            __syncthreads();
        }

        // ---- softmax per edge over 128 features ----
        {
            int et = tid >> 3, c = tid & 7;
            int t = et >> 4, e = et & 15;
            const float* ac = &attT[(t * 128) * FT2 + e];
            float m = -1e30f;
#pragma unroll 4
            for (int o = c*16; o < c*16+16; o++) m = fmaxf(m, ac[o*FT2]);
            sP[et][c] = m;
            __syncthreads();
            if (tid < 64) {
                float mm = sP[tid][0];
#pragma unroll
                for (int k = 1; k < 8; k++) mm = fmaxf(mm, sP[tid][k]);
                sm[tid] = mm;
            }
            __syncthreads();
            float mm = sm[et];
            float s = 0.f;
#pragma unroll 4
            for (int o = c*16; o < c*16+16; o++) s += __expf(ac[o*FT2] - mm);
            sP[et][c] = s;
            __syncthreads();
            if (tid < 64) {
                float ss = 0.f;
#pragma unroll
                for (int k = 0; k < 8; k++) ss += sP[tid][k];
                sv[tid] = 1.f / ss;
            }
            __syncthreads();
        }

        // ---- agg ----
        {
            int t = tid >> 7, o = tid & 127;
            const float* ar = &attT[(t * 128 + o) * FT2];
            const float* fr = &fijT[(t * 128 + o) * FT2];
            float a = 0.f;
#pragma unroll
            for (int e = 0; e < 16; e++) {
                int et = t * 16 + e;
                a += __expf(ar[e] - sm[et]) * sv[et] * fr[e];
            }
            aggS[t][o] = a;
        }
        __syncthreads();

        // ---- global: h2 = relu(agg @ Wg + bg), c-split=4 ----
        {
            int t = tid >> 7, q = (tid >> 2) & 31, c = tid & 3;
            u64 s0 = 0ull, s1 = 0ull;
#pragma unroll 4
            for (int ii = 0; ii < 32; ii++) {
                int i = c * 32 + ii;
                u64 xi = pk1(aggS[t][i]);
                s0 = ff2(xi, *(const u64*)&sWg[i*128 + 4*q],     s0);
                s1 = ff2(xi, *(const u64*)&sWg[i*128 + 4*q + 2], s1);
            }
            u64* scr = (u64*)attT;
            if (c) { scr[tid*2] = s0; scr[tid*2+1] = s1; }
            __syncthreads();
            if (c == 0) {
#pragma unroll
                for (int cc = 1; cc < 4; cc++) {
                    s0 = add2(s0, scr[(tid+cc)*2]);
                    s1 = add2(s1, scr[(tid+cc)*2+1]);
                }
                float2 v0 = upk(s0), v1 = upk(s1);
                int o = 4 * q;
                float* op = &g_h2[(size_t)(t0 + t) * 128 + o];
                op[0] = fmaxf(v0.x + sbg[o],   0.f);
                op[1] = fmaxf(v0.y + sbg[o+1], 0.f);
                op[2] = fmaxf(v1.x + sbg[o+2], 0.f);
                op[3] = fmaxf(v1.y + sbg[o+3], 0.f);
            }
            __syncthreads();
        }
    }
}

// ---------------------------------------------------------------------------
// tail: T=8 targets/iter, 512 threads, grid=148
// ---------------------------------------------------------------------------
#define TAIL_DYN_FLOATS (128*128 + 64*128)

__global__ void __launch_bounds__(512, 1)
tail_kernel(const float* __restrict__ x,
            const int*   __restrict__ idx1,
            const int*   __restrict__ idx2,
            const float* __restrict__ Wup, const float* __restrict__ bup,
            const float* __restrict__ Wsc, const float* __restrict__ bsc,
            float* __restrict__ out) {
    extern __shared__ float smem[];
    float* sWup = smem;               // 16384
    float* sWsc = smem + 16384;       // 8192

    __shared__ float sbup[128], sbsc[128];
    __shared__ float sh2[8 * 128];
    __shared__ float sx[8 * 64];
    __shared__ u64   scr[256 * 4];

    int tid = threadIdx.x;
    for (int i = tid; i < 16384; i += 512) sWup[i] = Wup[i];
    for (int i = tid; i < 8192;  i += 512) sWsc[i] = Wsc[i];
    if (tid < 128) { sbup[tid] = bup[tid]; sbsc[tid] = bsc[tid]; }
    __syncthreads();

    for (int t0 = blockIdx.x * 8; t0 < NN2; t0 += gridDim.x * 8) {
        sh2[tid]       = g_h2[(size_t)t0 * 128 + tid];
        sh2[tid + 512] = g_h2[(size_t)t0 * 128 + tid + 512];
        {
            int t = tid >> 6, f = tid & 63;
            int xr = idx1[idx2[t0 + t]];
            sx[t * 64 + f] = x[(size_t)xr * 64 + f];
        }
        __syncthreads();

        int t = tid >> 6;              // 8 targets
        int q = (tid >> 1) & 31;       // 32 output quads
        int c = tid & 1;               // i-half
        const float* h2r = &sh2[t * 128];
        const float* xrp = &sx[t * 64];

        u64 u0 = 0ull, u1 = 0ull;
#pragma unroll 4
        for (int ii = 0; ii < 64; ii++) {
            int i = c * 64 + ii;
            u64 xi = pk1(h2r[i]);
            u0 = ff2(xi, *(const u64*)&sWup[i*128 + 4*q],     u0);
            u1 = ff2(xi, *(const u64*)&sWup[i*128 + 4*q + 2], u1);
        }
        u64 s0 = 0ull, s1 = 0ull;
#pragma unroll 4
        for (int ii = 0; ii < 32; ii++) {
            int i = c * 32 + ii;
            u64 xi = pk1(xrp[i]);
            s0 = ff2(xi, *(const u64*)&sWsc[i*128 + 4*q],     s0);
            s1 = ff2(xi, *(const u64*)&sWsc[i*128 + 4*q + 2], s1);
        }
        int half = tid >> 1;
        if (c == 1) {
            scr[half*4+0] = u0; scr[half*4+1] = u1;
            scr[half*4+2] = s0; scr[half*4+3] = s1;
        }
        __syncthreads();
        if (c == 0) {
            u0 = add2(u0, scr[half*4+0]);
            u1 = add2(u1, scr[half*4+1]);
            s0 = add2(s0, scr[half*4+2]);
            s1 = add2(s1, scr[half*4+3]);
            float2 a0 = upk(u0), a1 = upk(u1), c0 = upk(s0), c1 = upk(s1);
            int o = 4 * q;
            float* op = &out[(size_t)(t0 + t) * 128 + o];
            op[0] = fmaxf(fmaxf(a0.x + sbup[o],   0.f) + fmaxf(c0.x + sbsc[o],   0.f), 0.f);
            op[1] = fmaxf(fmaxf(a0.y + sbup[o+1], 0.f) + fmaxf(c0.y + sbsc[o+1], 0.f), 0.f);
            op[2] = fmaxf(fmaxf(a1.x + sbup[o+2], 0.f) + fmaxf(c1.x + sbsc[o+2], 0.f), 0.f);
            op[3] = fmaxf(fmaxf(a1.y + sbup[o+3], 0.f) + fmaxf(c1.y + sbsc[o+3], 0.f), 0.f);
        }
        __syncthreads();
    }
}

// ---------------------------------------------------------------------------
extern "C" void kernel_launch(void* const* d_in, const int* in_sizes, int n_in,
                              void* d_out, int out_size) {
    const float* x      = (const float*)d_in[0];
    const float* pos    = (const float*)d_in[1];
    const float* W_down = (const float*)d_in[2];
    const float* b_down = (const float*)d_in[3];
    const float* W_pp1  = (const float*)d_in[4];
    const float* b_pp1  = (const float*)d_in[5];
    const float* W_att1 = (const float*)d_in[6];
    const float* b_att1 = (const float*)d_in[7];
    const float* W_g1   = (const float*)d_in[8];
    const float* b_g1   = (const float*)d_in[9];
    const float* W_pp2  = (const float*)d_in[10];
    const float* b_pp2  = (const float*)d_in[11];
    const float* W_att2 = (const float*)d_in[12];
    const float* b_att2 = (const float*)d_in[13];
    const float* W_g2   = (const float*)d_in[14];
    const float* b_g2   = (const float*)d_in[15];
    const float* W_up   = (const float*)d_in[16];
    const float* b_up   = (const float*)d_in[17];
    const float* W_sc   = (const float*)d_in[18];
    const float* b_sc   = (const float*)d_in[19];
    const int*   idx1   = (const int*)d_in[20];
    const int*   idx2   = (const int*)d_in[21];
    const int*   src1   = (const int*)d_in[22];
    const int*   src2   = (const int*)d_in[24];
    float* out = (float*)d_out;

    cudaFuncSetAttribute(conv1_kernel, cudaFuncAttributeMaxDynamicSharedMemorySize,
                         C1_DYN_FLOATS * (int)sizeof(float));
    cudaFuncSetAttribute(conv2_kernel, cudaFuncAttributeMaxDynamicSharedMemorySize,
                         C2_DYN_FLOATS * (int)sizeof(float));
    cudaFuncSetAttribute(tail_kernel, cudaFuncAttributeMaxDynamicSharedMemorySize,
                         TAIL_DYN_FLOATS * (int)sizeof(float));

    down_kernel<<<NPTS / 256, 256>>>(x, W_down, b_down);
    conv1_kernel<<<148, 512, C1_DYN_FLOATS * sizeof(float)>>>(
        pos, idx1, src1, W_pp1, b_pp1, W_att1, b_att1, W_g1, b_g1);
    conv2_kernel<<<148, 512, C2_DYN_FLOATS * sizeof(float)>>>(
        pos, idx1, idx2, src2, W_pp2, b_pp2, W_att2, b_att2, W_g2, b_g2);
    tail_kernel<<<148, 512, TAIL_DYN_FLOATS * sizeof(float)>>>(
        x, idx1, idx2, W_up, b_up, W_sc, b_sc, out);
}